// round 1
// baseline (speedup 1.0000x reference)
#include <cuda_runtime.h>
#include <math.h>

// Problem constants (shapes are fixed by the dataset)
#define BATCH 8
#define R 300
#define C 21
#define NC 20           // foreground classes
#define KPAD 21         // output pad size == num_classes
#define RW 10           // ceil(300/32) keep-bitmask words
#define SORT_N 512
#define NMS_T 0.3f

// Intermediate storage between the two kernels (allocation-free rule: device globals)
__device__ float4  g_sb[BATCH * NC * R];      // sorted+clipped boxes per (b, class)
__device__ unsigned g_keep[BATCH * NC * RW];  // keep bitmask per (b, class)

// ---------------------------------------------------------------------------
// Kernel 1: per (image, class) decode + sort + NMS.  grid = 160, block = 256.
// ---------------------------------------------------------------------------
__global__ __launch_bounds__(256) void decode_sort_nms_kernel(
    const float* __restrict__ cls_prob,   // [B,R,C]
    const float* __restrict__ rois,       // [B,R,5]
    const float* __restrict__ bbox_pred,  // [B,R,4C]
    const float* __restrict__ im_info,    // [B,3]
    const float* __restrict__ thr_arr)    // [C]
{
    __shared__ unsigned long long keys[SORT_N];
    __shared__ float4  box_sh[R];     // decoded boxes by original index
    __shared__ float4  sb_sh[R];      // boxes in sorted order
    __shared__ float   sm_sh[R];      // masked score by original index
    __shared__ float   ssm_sh[R];     // masked score in sorted order
    __shared__ float   area_sh[R];    // area in sorted order
    __shared__ unsigned mask_sh[R][RW];

    const int blk = blockIdx.x;
    const int b  = blk / NC;
    const int cc = blk % NC;        // 0..19
    const int c  = cc + 1;          // class id 1..20
    const int t  = threadIdx.x;

    const float thr = thr_arr[c];
    const float H1 = im_info[b * 3 + 0] - 1.0f;
    const float W1 = im_info[b * 3 + 1] - 1.0f;

    // --- decode + clip + build sort keys ---
    for (int r = t; r < R; r += 256) {
        const float* rp = rois + (size_t)(b * R + r) * 5;
        float x1 = rp[1], y1 = rp[2], x2 = rp[3], y2 = rp[4];
        float w  = x2 - x1 + 1.0f;
        float h  = y2 - y1 + 1.0f;
        float cx = x1 + 0.5f * w;
        float cy = y1 + 0.5f * h;

        const float* dp = bbox_pred + (size_t)(b * R + r) * (4 * C) + 4 * c;
        float d0 = dp[0] * 0.1f;
        float d1 = dp[1] * 0.1f;
        float d2 = dp[2] * 0.2f;
        float d3 = dp[3] * 0.2f;

        float pcx = d0 * w + cx;
        float pcy = d1 * h + cy;
        float pw  = expf(d2) * w;
        float ph  = expf(d3) * h;

        float bx1 = fminf(fmaxf(pcx - 0.5f * pw, 0.0f), W1);
        float by1 = fminf(fmaxf(pcy - 0.5f * ph, 0.0f), H1);
        float bx2 = fminf(fmaxf(pcx + 0.5f * pw, 0.0f), W1);
        float by2 = fminf(fmaxf(pcy + 0.5f * ph, 0.0f), H1);
        box_sh[r] = make_float4(bx1, by1, bx2, by2);

        float s  = cls_prob[(size_t)(b * R + r) * C + c];
        float sm = (s > thr) ? s : -INFINITY;
        sm_sh[r] = sm;

        // monotone float->uint (ascending), inverted for descending sort;
        // low 32 bits = index => stable tie-break by ascending original index.
        unsigned u = __float_as_uint(sm);
        unsigned m = (u & 0x80000000u) ? ~u : (u | 0x80000000u);
        keys[r] = (((unsigned long long)(~m)) << 32) | (unsigned)r;
    }
    for (int r = R + t; r < SORT_N; r += 256) keys[r] = ~0ULL;  // padding sorts last
    __syncthreads();

    // --- bitonic sort 512 keys ascending ---
    for (int k = 2; k <= SORT_N; k <<= 1) {
        for (int j = k >> 1; j > 0; j >>= 1) {
            for (int i = t; i < SORT_N; i += 256) {
                int l = i ^ j;
                if (l > i) {
                    unsigned long long a = keys[i], bb = keys[l];
                    bool asc = ((i & k) == 0);
                    if ((a > bb) == asc) { keys[i] = bb; keys[l] = a; }
                }
            }
            __syncthreads();
        }
    }

    // --- gather sorted boxes / scores / areas ---
    for (int i = t; i < R; i += 256) {
        int idx = (int)(keys[i] & 0xFFFFFFFFu);
        float4 bb = box_sh[idx];
        sb_sh[i]  = bb;
        ssm_sh[i] = sm_sh[idx];
        area_sh[i] = (bb.z - bb.x + 1.0f) * (bb.w - bb.y + 1.0f);
    }
    __syncthreads();

    // --- suppression bitmask: mask[i][w] bit j set iff IoU(i, w*32+j) > T and (w*32+j) > i
    for (int task = t; task < R * RW; task += 256) {
        int i = task / RW;
        int w = task % RW;
        float4 bi = sb_sh[i];
        float  ai = area_sh[i];
        unsigned bits = 0;
        int j0 = w * 32;
        int jend = min(j0 + 32, R);
        int jstart = (j0 > i) ? j0 : (i + 1);
        for (int j = jstart; j < jend; j++) {
            float4 bj = sb_sh[j];
            float ix1 = fmaxf(bi.x, bj.x);
            float iy1 = fmaxf(bi.y, bj.y);
            float ix2 = fminf(bi.z, bj.z);
            float iy2 = fminf(bi.w, bj.w);
            float iw = fmaxf(ix2 - ix1 + 1.0f, 0.0f);
            float ih = fmaxf(iy2 - iy1 + 1.0f, 0.0f);
            float inter = iw * ih;
            float iou = inter / (ai + area_sh[j] - inter);
            if (iou > NMS_T) bits |= (1u << (j - j0));
        }
        mask_sh[i][w] = bits;
    }
    __syncthreads();

    // --- serial greedy scan (the only inherently sequential step) ---
    if (t == 0) {
        unsigned rem[RW]  = {0};
        unsigned kout[RW] = {0};
        for (int i = 0; i < R; i++) {
            if (ssm_sh[i] > thr && !((rem[i >> 5] >> (i & 31)) & 1u)) {
                kout[i >> 5] |= (1u << (i & 31));
                #pragma unroll
                for (int w = 0; w < RW; w++) rem[w] |= mask_sh[i][w];
            }
        }
        #pragma unroll
        for (int w = 0; w < RW; w++) g_keep[(b * NC + cc) * RW + w] = kout[w];
    }

    // --- write sorted boxes for the selection kernel ---
    for (int i = t; i < R; i += 256) {
        g_sb[(b * NC + cc) * R + i] = sb_sh[i];
    }
}

// ---------------------------------------------------------------------------
// Kernel 2: per image, select first K kept detections in (class, rank) order.
// grid = 8, block = 32.
// ---------------------------------------------------------------------------
__global__ void select_kernel(float* __restrict__ out, int out_size)
{
    const int b = blockIdx.x;
    const int t = threadIdx.x;

    // zero this image's [K,5] slab
    for (int i = t; i < KPAD * 5; i += 32) out[b * (KPAD * 5) + i] = 0.0f;
    __syncwarp();

    if (t == 0) {
        int cnt = 0;
        for (int cc = 0; cc < NC && cnt < KPAD; cc++) {
            for (int w = 0; w < RW && cnt < KPAD; w++) {
                unsigned bits = g_keep[(b * NC + cc) * RW + w];
                while (bits && cnt < KPAD) {
                    int j = __ffs(bits) - 1;
                    bits &= bits - 1;
                    int i = w * 32 + j;
                    float4 bb = g_sb[(b * NC + cc) * R + i];
                    float* o = out + b * (KPAD * 5) + cnt * 5;
                    o[0] = bb.x; o[1] = bb.y; o[2] = bb.z; o[3] = bb.w;
                    o[4] = (float)(cc + 1);
                    cnt++;
                }
            }
        }
        // n output (counts), appended after the [B,K,5] block, if present
        int base = BATCH * KPAD * 5;
        if (out_size >= base + BATCH) out[base + b] = (float)cnt;
    }
}

// ---------------------------------------------------------------------------
extern "C" void kernel_launch(void* const* d_in, const int* in_sizes, int n_in,
                              void* d_out, int out_size)
{
    const float* cls_prob  = (const float*)d_in[0];
    const float* rois      = (const float*)d_in[1];
    const float* bbox_pred = (const float*)d_in[2];
    const float* im_info   = (const float*)d_in[3];
    const float* thr       = (const float*)d_in[4];
    // d_in[5] = num_classes (compile-time constant here)

    float* out = (float*)d_out;

    decode_sort_nms_kernel<<<BATCH * NC, 256>>>(cls_prob, rois, bbox_pred, im_info, thr);
    select_kernel<<<BATCH, 32>>>(out, out_size);
}

// round 2
// speedup vs baseline: 1.7253x; 1.7253x over previous
#include <cuda_runtime.h>
#include <math.h>

// Problem constants (shapes fixed by the dataset)
#define BATCH 8
#define R 300
#define C 21
#define NC 20           // foreground classes
#define KPAD 21         // output pad size == num_classes
#define RW 10           // ceil(300/32) keep-bitmask words
#define NMS_T 0.3f

// Cross-block intermediates (allocation-free rule: device globals)
__device__ float4   g_sb[BATCH * NC * R];      // sorted+clipped boxes per (b,class)
__device__ unsigned g_keep[BATCH * NC * RW];   // keep bitmask per (b,class)
__device__ int      g_ctr[BATCH];              // arrival counters (self-resetting)

__global__ __launch_bounds__(256) void fused_nms_kernel(
    const float* __restrict__ cls_prob,   // [B,R,C]
    const float* __restrict__ rois,       // [B,R,5]
    const float* __restrict__ bbox_pred,  // [B,R,4C]
    const float* __restrict__ im_info,    // [B,3]
    const float* __restrict__ thr_arr,    // [C]
    float* __restrict__ out, int out_size)
{
    __shared__ unsigned long long keys[R];
    __shared__ float4  box_sh[R];           // decoded boxes by original index
    __shared__ float4  sb_sh[R];            // boxes in sorted order
    __shared__ float   area_sh[R];          // areas in sorted order
    __shared__ unsigned mask_sh[R][RW];     // suppression bitmask (valid prefix only)
    __shared__ int sV;
    __shared__ int sOld;

    const int blk = blockIdx.x;
    const int b   = blk / NC;
    const int cc  = blk % NC;      // 0..19
    const int c   = cc + 1;        // class id 1..20
    const int t   = threadIdx.x;
    const int lane = t & 31;
    const int wid  = t >> 5;

    const float thr = thr_arr[c];
    const float H1 = im_info[b * 3 + 0] - 1.0f;
    const float W1 = im_info[b * 3 + 1] - 1.0f;

    if (t == 0) sV = 0;
    __syncthreads();

    // ---- decode + clip + build sort key (identical arithmetic to passing R1) ----
    auto decode_row = [&](int r) -> int {
        const float* rp = rois + (size_t)(b * R + r) * 5;
        float x1 = rp[1], y1 = rp[2], x2 = rp[3], y2 = rp[4];
        float w  = x2 - x1 + 1.0f;
        float h  = y2 - y1 + 1.0f;
        float cx = x1 + 0.5f * w;
        float cy = y1 + 0.5f * h;

        const float* dp = bbox_pred + (size_t)(b * R + r) * (4 * C) + 4 * c;
        float d0 = dp[0] * 0.1f;
        float d1 = dp[1] * 0.1f;
        float d2 = dp[2] * 0.2f;
        float d3 = dp[3] * 0.2f;

        float pcx = d0 * w + cx;
        float pcy = d1 * h + cy;
        float pw  = expf(d2) * w;
        float ph  = expf(d3) * h;

        float bx1 = fminf(fmaxf(pcx - 0.5f * pw, 0.0f), W1);
        float by1 = fminf(fmaxf(pcy - 0.5f * ph, 0.0f), H1);
        float bx2 = fminf(fmaxf(pcx + 0.5f * pw, 0.0f), W1);
        float by2 = fminf(fmaxf(pcy + 0.5f * ph, 0.0f), H1);
        box_sh[r] = make_float4(bx1, by1, bx2, by2);

        float s  = cls_prob[(size_t)(b * R + r) * C + c];
        int   valid = (s > thr) ? 1 : 0;
        float sm = valid ? s : -INFINITY;

        // monotone float->uint, inverted => ascending sort == descending score,
        // low 32 bits = original index (stable tie-break).
        unsigned u = __float_as_uint(sm);
        unsigned m = (u & 0x80000000u) ? ~u : (u | 0x80000000u);
        keys[r] = (((unsigned long long)(~m)) << 32) | (unsigned)r;
        return valid;
    };

    int v = decode_row(t);
    int r1 = t + 256;
    if (r1 < R) v += decode_row(r1);
    atomicAdd(&sV, v);
    __syncthreads();

    const int V  = sV;
    const int VW = (V + 31) >> 5;

    // ---- enumeration (rank) sort: zero barriers inside ----
    {
        unsigned long long k0 = keys[t];
        unsigned long long k1 = (r1 < R) ? keys[r1] : ~0ULL;
        int c0 = 0, c1 = 0;
        #pragma unroll 4
        for (int j = 0; j < R; j++) {
            unsigned long long kj = keys[j];   // broadcast LDS
            c0 += (kj < k0);
            c1 += (kj < k1);
        }
        float4 bb0 = box_sh[t];
        sb_sh[c0] = bb0;
        area_sh[c0] = (bb0.z - bb0.x + 1.0f) * (bb0.w - bb0.y + 1.0f);
        if (r1 < R) {
            float4 bb1 = box_sh[r1];
            sb_sh[c1] = bb1;
            area_sh[c1] = (bb1.z - bb1.x + 1.0f) * (bb1.w - bb1.y + 1.0f);
        }
    }
    __syncthreads();

    // ---- publish sorted boxes (valid prefix only) for cross-block selection ----
    for (int i = t; i < V; i += 256)
        __stcg(&g_sb[(size_t)(b * NC + cc) * R + i], sb_sh[i]);

    // ---- suppression bitmask on the valid prefix, warp-ballot per 32-j chunk ----
    for (int i = wid; i < V; i += 8) {
        float4 bi = sb_sh[i];
        float  ai = area_sh[i];
        for (int jw = (i >> 5); jw < VW; jw++) {
            int j = (jw << 5) + lane;
            bool sup = false;
            if (j > i && j < V) {
                float4 bj = sb_sh[j];
                float ix1 = fmaxf(bi.x, bj.x);
                float iy1 = fmaxf(bi.y, bj.y);
                float ix2 = fminf(bi.z, bj.z);
                float iy2 = fminf(bi.w, bj.w);
                float iw = fmaxf(ix2 - ix1 + 1.0f, 0.0f);
                float ih = fmaxf(iy2 - iy1 + 1.0f, 0.0f);
                float inter = iw * ih;
                float iou = inter / (ai + area_sh[j] - inter);
                sup = (iou > NMS_T);
            }
            unsigned bits = __ballot_sync(0xffffffffu, sup);
            if (lane == 0) mask_sh[i][jw] = bits;
        }
    }
    __syncthreads();

    // ---- serial greedy scan over the valid prefix (single thread) ----
    if (t == 0) {
        unsigned rem[RW], kout[RW];
        #pragma unroll
        for (int w = 0; w < RW; w++) { rem[w] = 0u; kout[w] = 0u; }
        for (int i = 0; i < V; i++) {
            if (!((rem[i >> 5] >> (i & 31)) & 1u)) {
                kout[i >> 5] |= (1u << (i & 31));
                for (int w = (i >> 5); w < VW; w++) rem[w] |= mask_sh[i][w];
            }
        }
        #pragma unroll
        for (int w = 0; w < RW; w++)
            __stcg(&g_keep[(b * NC + cc) * RW + w], kout[w]);
    }

    // ---- release writes, arrive; last block per image does selection ----
    __threadfence();
    __syncthreads();
    if (t == 0) {
        sOld = atomicAdd(&g_ctr[b], 1);
        __threadfence();
    }
    __syncthreads();

    if (sOld == NC - 1) {
        if (t < 32) {
            int cls = lane;     // 0..19 valid
            int cnt = 0;
            unsigned kw[RW];
            if (cls < NC) {
                #pragma unroll
                for (int w = 0; w < RW; w++) {
                    kw[w] = __ldcg(&g_keep[(b * NC + cls) * RW + w]);
                    cnt += __popc(kw[w]);
                }
            }
            // warp inclusive scan of counts
            int incl = cnt;
            #pragma unroll
            for (int off = 1; off < 32; off <<= 1) {
                int n = __shfl_up_sync(0xffffffffu, incl, off);
                if (lane >= off) incl += n;
            }
            int total = __shfl_sync(0xffffffffu, incl, 31);
            int excl  = incl - cnt;

            // zero this image's [K,5] slab
            for (int i = lane; i < KPAD * 5; i += 32)
                out[b * (KPAD * 5) + i] = 0.0f;
            __syncwarp();

            if (cls < NC && cnt > 0 && excl < KPAD) {
                int slot = excl;
                float clsf = (float)(cls + 1);
                for (int w = 0; w < RW && slot < KPAD; w++) {
                    unsigned bits = kw[w];
                    while (bits && slot < KPAD) {
                        int j = __ffs(bits) - 1;
                        bits &= bits - 1;
                        float4 bb = __ldcg(&g_sb[(size_t)(b * NC + cls) * R + (w << 5) + j]);
                        float* o = out + b * (KPAD * 5) + slot * 5;
                        o[0] = bb.x; o[1] = bb.y; o[2] = bb.z; o[3] = bb.w;
                        o[4] = clsf;
                        slot++;
                    }
                }
            }
            if (lane == 0) {
                int nbase = BATCH * KPAD * 5;
                if (out_size >= nbase + BATCH)
                    out[nbase + b] = (float)min(total, KPAD);
                g_ctr[b] = 0;   // self-reset for next graph replay
            }
        }
    }
}

extern "C" void kernel_launch(void* const* d_in, const int* in_sizes, int n_in,
                              void* d_out, int out_size)
{
    (void)in_sizes; (void)n_in;
    const float* cls_prob  = (const float*)d_in[0];
    const float* rois      = (const float*)d_in[1];
    const float* bbox_pred = (const float*)d_in[2];
    const float* im_info   = (const float*)d_in[3];
    const float* thr       = (const float*)d_in[4];

    fused_nms_kernel<<<BATCH * NC, 256>>>(cls_prob, rois, bbox_pred, im_info, thr,
                                          (float*)d_out, out_size);
}

// round 3
// speedup vs baseline: 2.2809x; 1.3220x over previous
#include <cuda_runtime.h>
#include <math.h>

// Problem constants (shapes fixed by the dataset)
#define BATCH 8
#define R 300
#define C 21
#define NC 20           // foreground classes
#define KPAD 21         // output pad size == num_classes
#define RW 10           // ceil(300/32) keep-bitmask words
#define NMS_T 0.3f

// Cross-block intermediates (allocation-free rule: device globals)
__device__ float4   g_sb[BATCH * NC * R];      // sorted+clipped boxes per (b,class)
__device__ unsigned g_keep[BATCH * NC * RW];   // keep bitmask per (b,class)
__device__ int      g_ctr[BATCH];              // arrival counters (self-resetting)

__global__ __launch_bounds__(256) void fused_nms_kernel(
    const float* __restrict__ cls_prob,   // [B,R,C]
    const float* __restrict__ rois,       // [B,R,5]
    const float* __restrict__ bbox_pred,  // [B,R,4C]
    const float* __restrict__ im_info,    // [B,3]
    const float* __restrict__ thr_arr,    // [C]
    float* __restrict__ out, int out_size)
{
    __shared__ unsigned long long keys[R];
    __shared__ float4  box_sh[R];           // decoded boxes by original index
    __shared__ float4  sb_sh[R];            // boxes in sorted order
    __shared__ float   area_sh[R];          // areas in sorted order
    __shared__ unsigned mask_sh[R][RW];     // suppression bitmask (valid prefix only)
    __shared__ int sV;
    __shared__ int sOld;

    const int blk = blockIdx.x;
    const int b   = blk / NC;
    const int cc  = blk % NC;      // 0..19
    const int c   = cc + 1;        // class id 1..20
    const int t   = threadIdx.x;
    const int lane = t & 31;
    const int wid  = t >> 5;

    const float thr = thr_arr[c];
    const float H1 = im_info[b * 3 + 0] - 1.0f;
    const float W1 = im_info[b * 3 + 1] - 1.0f;

    if (t == 0) sV = 0;
    __syncthreads();

    // ---- decode + clip + build sort key (identical arithmetic to passing R1) ----
    auto decode_row = [&](int r) -> int {
        const float* rp = rois + (size_t)(b * R + r) * 5;
        float x1 = rp[1], y1 = rp[2], x2 = rp[3], y2 = rp[4];
        float w  = x2 - x1 + 1.0f;
        float h  = y2 - y1 + 1.0f;
        float cx = x1 + 0.5f * w;
        float cy = y1 + 0.5f * h;

        const float* dp = bbox_pred + (size_t)(b * R + r) * (4 * C) + 4 * c;
        float d0 = dp[0] * 0.1f;
        float d1 = dp[1] * 0.1f;
        float d2 = dp[2] * 0.2f;
        float d3 = dp[3] * 0.2f;

        float pcx = d0 * w + cx;
        float pcy = d1 * h + cy;
        float pw  = expf(d2) * w;
        float ph  = expf(d3) * h;

        float bx1 = fminf(fmaxf(pcx - 0.5f * pw, 0.0f), W1);
        float by1 = fminf(fmaxf(pcy - 0.5f * ph, 0.0f), H1);
        float bx2 = fminf(fmaxf(pcx + 0.5f * pw, 0.0f), W1);
        float by2 = fminf(fmaxf(pcy + 0.5f * ph, 0.0f), H1);
        box_sh[r] = make_float4(bx1, by1, bx2, by2);

        float s  = cls_prob[(size_t)(b * R + r) * C + c];
        int   valid = (s > thr) ? 1 : 0;
        float sm = valid ? s : -INFINITY;

        // monotone float->uint, inverted => ascending sort == descending score,
        // low 32 bits = original index (stable tie-break).
        unsigned u = __float_as_uint(sm);
        unsigned m = (u & 0x80000000u) ? ~u : (u | 0x80000000u);
        keys[r] = (((unsigned long long)(~m)) << 32) | (unsigned)r;
        return valid;
    };

    int v = decode_row(t);
    int r1 = t + 256;
    if (r1 < R) v += decode_row(r1);
    // warp-aggregate the valid count, then one atomic per warp
    {
        #pragma unroll
        for (int off = 16; off > 0; off >>= 1)
            v += __shfl_down_sync(0xffffffffu, v, off);
        if (lane == 0) atomicAdd(&sV, v);
    }
    __syncthreads();

    const int V  = sV;
    const int VW = (V + 31) >> 5;

    // ---- enumeration (rank) sort: zero barriers inside ----
    {
        unsigned long long k0 = keys[t];
        unsigned long long k1 = (r1 < R) ? keys[r1] : ~0ULL;
        int c0 = 0, c1 = 0;
        #pragma unroll 4
        for (int j = 0; j < R; j++) {
            unsigned long long kj = keys[j];   // broadcast LDS
            c0 += (kj < k0);
            c1 += (kj < k1);
        }
        float4 bb0 = box_sh[t];
        sb_sh[c0] = bb0;
        area_sh[c0] = (bb0.z - bb0.x + 1.0f) * (bb0.w - bb0.y + 1.0f);
        if (r1 < R) {
            float4 bb1 = box_sh[r1];
            sb_sh[c1] = bb1;
            area_sh[c1] = (bb1.z - bb1.x + 1.0f) * (bb1.w - bb1.y + 1.0f);
        }
    }
    __syncthreads();

    // ---- publish sorted boxes (valid prefix only) for cross-block selection ----
    for (int i = t; i < V; i += 256)
        __stcg(&g_sb[(size_t)(b * NC + cc) * R + i], sb_sh[i]);

    // ---- suppression bitmask on the valid prefix, warp-ballot per 32-j chunk ----
    for (int i = wid; i < V; i += 8) {
        float4 bi = sb_sh[i];
        float  ai = area_sh[i];
        for (int jw = (i >> 5); jw < VW; jw++) {
            int j = (jw << 5) + lane;
            bool sup = false;
            if (j > i && j < V) {
                float4 bj = sb_sh[j];
                float ix1 = fmaxf(bi.x, bj.x);
                float iy1 = fmaxf(bi.y, bj.y);
                float ix2 = fminf(bi.z, bj.z);
                float iy2 = fminf(bi.w, bj.w);
                float iw = fmaxf(ix2 - ix1 + 1.0f, 0.0f);
                float ih = fmaxf(iy2 - iy1 + 1.0f, 0.0f);
                float inter = iw * ih;
                float iou = inter / (ai + area_sh[j] - inter);
                sup = (iou > NMS_T);
            }
            unsigned bits = __ballot_sync(0xffffffffu, sup);
            if (lane == 0) mask_sh[i][jw] = bits;
        }
    }
    __syncthreads();

    // ---- warp-parallel greedy scan, kept-only iterations ----
    // Lane w owns bitmask word w. "live" = valid and not yet suppressed/kept.
    // The first live box in sorted order is exactly the next greedy keep.
    if (t < 32) {
        unsigned live = 0;
        {
            int lo = lane << 5;
            int hi = min(V, lo + 32);
            if (hi > lo) live = (hi - lo == 32) ? 0xffffffffu : ((1u << (hi - lo)) - 1u);
        }
        unsigned kout = 0;
        while (true) {
            unsigned act = __ballot_sync(0xffffffffu, live != 0u);
            if (!act) break;
            int w0  = __ffs(act) - 1;
            unsigned lw = __shfl_sync(0xffffffffu, live, w0);
            int bit = __ffs(lw) - 1;
            int i   = (w0 << 5) + bit;
            if (lane == w0) {
                kout |= (1u << bit);
                live &= ~(1u << bit);
            }
            // AND-clear suppressed. Unwritten mask words only touch bits that
            // are provably already 0 (all j < i are non-live), so this is safe.
            unsigned sup = (lane < RW) ? mask_sh[i][lane] : 0u;
            live &= ~sup;
        }
        if (lane < RW)
            __stcg(&g_keep[(b * NC + cc) * RW + lane], kout);
    }

    // ---- release writes, arrive; last block per image does selection ----
    __threadfence();
    __syncthreads();
    if (t == 0) {
        sOld = atomicAdd(&g_ctr[b], 1);
        __threadfence();
    }
    __syncthreads();

    if (sOld == NC - 1) {
        if (t < 32) {
            int cls = lane;     // 0..19 valid
            int cnt = 0;
            unsigned kw[RW];
            if (cls < NC) {
                #pragma unroll
                for (int w = 0; w < RW; w++) {
                    kw[w] = __ldcg(&g_keep[(b * NC + cls) * RW + w]);
                    cnt += __popc(kw[w]);
                }
            }
            // warp inclusive scan of counts
            int incl = cnt;
            #pragma unroll
            for (int off = 1; off < 32; off <<= 1) {
                int n = __shfl_up_sync(0xffffffffu, incl, off);
                if (lane >= off) incl += n;
            }
            int total = __shfl_sync(0xffffffffu, incl, 31);
            int excl  = incl - cnt;

            // zero this image's [K,5] slab
            for (int i = lane; i < KPAD * 5; i += 32)
                out[b * (KPAD * 5) + i] = 0.0f;
            __syncwarp();

            if (cls < NC && cnt > 0 && excl < KPAD) {
                int slot = excl;
                float clsf = (float)(cls + 1);
                for (int w = 0; w < RW && slot < KPAD; w++) {
                    unsigned bits = kw[w];
                    while (bits && slot < KPAD) {
                        int j = __ffs(bits) - 1;
                        bits &= bits - 1;
                        float4 bb = __ldcg(&g_sb[(size_t)(b * NC + cls) * R + (w << 5) + j]);
                        float* o = out + b * (KPAD * 5) + slot * 5;
                        o[0] = bb.x; o[1] = bb.y; o[2] = bb.z; o[3] = bb.w;
                        o[4] = clsf;
                        slot++;
                    }
                }
            }
            if (lane == 0) {
                int nbase = BATCH * KPAD * 5;
                if (out_size >= nbase + BATCH)
                    out[nbase + b] = (float)min(total, KPAD);
                g_ctr[b] = 0;   // self-reset for next graph replay
            }
        }
    }
}

extern "C" void kernel_launch(void* const* d_in, const int* in_sizes, int n_in,
                              void* d_out, int out_size)
{
    (void)in_sizes; (void)n_in;
    const float* cls_prob  = (const float*)d_in[0];
    const float* rois      = (const float*)d_in[1];
    const float* bbox_pred = (const float*)d_in[2];
    const float* im_info   = (const float*)d_in[3];
    const float* thr       = (const float*)d_in[4];

    fused_nms_kernel<<<BATCH * NC, 256>>>(cls_prob, rois, bbox_pred, im_info, thr,
                                          (float*)d_out, out_size);
}

// round 4
// speedup vs baseline: 3.0423x; 1.3338x over previous
#include <cuda_runtime.h>
#include <math.h>

// Problem constants (shapes fixed by the dataset)
#define BATCH 8
#define R 300
#define C 21
#define NC 20           // foreground classes
#define KPAD 21         // output pad size == num_classes
#define RW 10           // ceil(300/32) keep-bitmask words
#define NMS_T 0.3f
#define NT 512          // threads per block
#define NW 16           // warps per block

// Cross-block intermediates (allocation-free rule: device globals)
__device__ float4   g_sb[BATCH * NC * R];      // sorted+clipped boxes per (b,class)
__device__ unsigned g_keep[BATCH * NC * RW];   // keep bitmask per (b,class)
__device__ int      g_ctr[BATCH];              // arrival counters (self-resetting)

__global__ __launch_bounds__(NT) void fused_nms_kernel(
    const float* __restrict__ cls_prob,   // [B,R,C]
    const float* __restrict__ rois,       // [B,R,5]
    const float* __restrict__ bbox_pred,  // [B,R,4C]
    const float* __restrict__ im_info,    // [B,3]
    const float* __restrict__ thr_arr,    // [C]
    float* __restrict__ out, int out_size)
{
    __shared__ unsigned long long ckeys[R];   // compacted valid keys, index order
    __shared__ float4  box_sh[R];             // decoded boxes by original index
    __shared__ float4  sb_sh[R];              // boxes in sorted order (valid prefix)
    __shared__ float   area_sh[R];            // areas in sorted order
    __shared__ unsigned mask_sh[R][RW];       // suppression bitmask (valid prefix)
    __shared__ int warpcnt[NW];
    __shared__ int warpoff[NW];
    __shared__ int sV;
    __shared__ int sOld;

    const int blk = blockIdx.x;
    const int b   = blk / NC;
    const int cc  = blk % NC;      // 0..19
    const int c   = cc + 1;        // class id 1..20
    const int t   = threadIdx.x;
    const int lane = t & 31;
    const int wid  = t >> 5;

    const float thr = thr_arr[c];
    const float H1 = im_info[b * 3 + 0] - 1.0f;
    const float W1 = im_info[b * 3 + 1] - 1.0f;

    // ---- decode + clip + key (one row per thread; arithmetic identical to R1) ----
    int valid = 0;
    unsigned long long key = ~0ULL;
    const int r = t;
    if (r < R) {
        const float* rp = rois + (size_t)(b * R + r) * 5;
        float x1 = rp[1], y1 = rp[2], x2 = rp[3], y2 = rp[4];
        float w  = x2 - x1 + 1.0f;
        float h  = y2 - y1 + 1.0f;
        float cx = x1 + 0.5f * w;
        float cy = y1 + 0.5f * h;

        const float* dp = bbox_pred + (size_t)(b * R + r) * (4 * C) + 4 * c;
        float d0 = dp[0] * 0.1f;
        float d1 = dp[1] * 0.1f;
        float d2 = dp[2] * 0.2f;
        float d3 = dp[3] * 0.2f;

        float pcx = d0 * w + cx;
        float pcy = d1 * h + cy;
        float pw  = expf(d2) * w;
        float ph  = expf(d3) * h;

        float bx1 = fminf(fmaxf(pcx - 0.5f * pw, 0.0f), W1);
        float by1 = fminf(fmaxf(pcy - 0.5f * ph, 0.0f), H1);
        float bx2 = fminf(fmaxf(pcx + 0.5f * pw, 0.0f), W1);
        float by2 = fminf(fmaxf(pcy + 0.5f * ph, 0.0f), H1);
        box_sh[r] = make_float4(bx1, by1, bx2, by2);

        float s = cls_prob[(size_t)(b * R + r) * C + c];
        valid = (s > thr) ? 1 : 0;

        // monotone float->uint, inverted => ascending sort == descending score,
        // low 32 bits = original index (stable tie-break).
        unsigned u = __float_as_uint(s);
        unsigned m = (u & 0x80000000u) ? ~u : (u | 0x80000000u);
        key = (((unsigned long long)(~m)) << 32) | (unsigned)r;
    }

    // ---- stable compaction of valid rows (index order preserved) ----
    unsigned bal = __ballot_sync(0xffffffffu, valid);
    if (lane == 0) warpcnt[wid] = __popc(bal);
    __syncthreads();
    if (t < NW) {
        int v = warpcnt[t];
        int incl = v;
        #pragma unroll
        for (int off = 1; off < NW; off <<= 1) {
            int n = __shfl_up_sync(0x0000ffffu, incl, off);
            if (t >= off) incl += n;
        }
        warpoff[t] = incl - v;
        if (t == NW - 1) sV = incl;
    }
    __syncthreads();
    const int V  = sV;
    const int VW = (V + 31) >> 5;

    if (valid) {
        int pos = warpoff[wid] + __popc(bal & ((1u << lane) - 1u));
        ckeys[pos] = key;
    }
    __syncthreads();

    // ---- enumeration (rank) sort over the V compacted keys ----
    if (t < V) {
        unsigned long long k0 = ckeys[t];
        int rank = 0;
        #pragma unroll 4
        for (int j = 0; j < V; j++)
            rank += (ckeys[j] < k0);
        int orig = (int)(k0 & 0xFFFFFFFFu);
        float4 bb = box_sh[orig];
        sb_sh[rank] = bb;
        area_sh[rank] = (bb.z - bb.x + 1.0f) * (bb.w - bb.y + 1.0f);
    }
    __syncthreads();

    // ---- publish sorted boxes (valid prefix) for cross-block selection ----
    if (t < V)
        __stcg(&g_sb[(size_t)(b * NC + cc) * R + t], sb_sh[t]);

    // ---- suppression bitmask on the valid prefix, warp-ballot per 32-j chunk ----
    for (int i = wid; i < V; i += NW) {
        float4 bi = sb_sh[i];
        float  ai = area_sh[i];
        for (int jw = (i >> 5); jw < VW; jw++) {
            int j = (jw << 5) + lane;
            bool sup = false;
            if (j > i && j < V) {
                float4 bj = sb_sh[j];
                float ix1 = fmaxf(bi.x, bj.x);
                float iy1 = fmaxf(bi.y, bj.y);
                float ix2 = fminf(bi.z, bj.z);
                float iy2 = fminf(bi.w, bj.w);
                float iw = fmaxf(ix2 - ix1 + 1.0f, 0.0f);
                float ih = fmaxf(iy2 - iy1 + 1.0f, 0.0f);
                float inter = iw * ih;
                float iou = inter / (ai + area_sh[j] - inter);
                sup = (iou > NMS_T);
            }
            unsigned bits = __ballot_sync(0xffffffffu, sup);
            if (lane == 0) mask_sh[i][jw] = bits;
        }
    }
    __syncthreads();

    // ---- warp-parallel greedy scan, kept-only iterations ----
    if (t < 32) {
        unsigned live = 0;
        {
            int lo = lane << 5;
            int hi = min(V, lo + 32);
            if (hi > lo) live = (hi - lo == 32) ? 0xffffffffu : ((1u << (hi - lo)) - 1u);
        }
        unsigned kout = 0;
        while (true) {
            unsigned act = __ballot_sync(0xffffffffu, live != 0u);
            if (!act) break;
            int w0  = __ffs(act) - 1;
            unsigned lw = __shfl_sync(0xffffffffu, live, w0);
            int bit = __ffs(lw) - 1;
            int i   = (w0 << 5) + bit;
            if (lane == w0) {
                kout |= (1u << bit);
                live &= ~(1u << bit);
            }
            // AND-clear suppressed. Unwritten mask words only touch bits that
            // are provably already 0 (all j < i are non-live), so this is safe.
            unsigned sup = (lane < RW) ? mask_sh[i][lane] : 0u;
            live &= ~sup;
        }
        if (lane < RW)
            __stcg(&g_keep[(b * NC + cc) * RW + lane], kout);
    }

    // ---- release writes, arrive; last block per image does selection ----
    __threadfence();
    __syncthreads();
    if (t == 0) {
        sOld = atomicAdd(&g_ctr[b], 1);
        __threadfence();
    }
    __syncthreads();

    if (sOld == NC - 1) {
        if (t < 32) {
            int cls = lane;     // 0..19 valid
            int cnt = 0;
            unsigned kw[RW];
            if (cls < NC) {
                #pragma unroll
                for (int w = 0; w < RW; w++) {
                    kw[w] = __ldcg(&g_keep[(b * NC + cls) * RW + w]);
                    cnt += __popc(kw[w]);
                }
            }
            // warp inclusive scan of counts
            int incl = cnt;
            #pragma unroll
            for (int off = 1; off < 32; off <<= 1) {
                int n = __shfl_up_sync(0xffffffffu, incl, off);
                if (lane >= off) incl += n;
            }
            int total = __shfl_sync(0xffffffffu, incl, 31);
            int excl  = incl - cnt;

            // zero this image's [K,5] slab
            for (int i = lane; i < KPAD * 5; i += 32)
                out[b * (KPAD * 5) + i] = 0.0f;
            __syncwarp();

            if (cls < NC && cnt > 0 && excl < KPAD) {
                int slot = excl;
                float clsf = (float)(cls + 1);
                for (int w = 0; w < RW && slot < KPAD; w++) {
                    unsigned bits = kw[w];
                    while (bits && slot < KPAD) {
                        int j = __ffs(bits) - 1;
                        bits &= bits - 1;
                        float4 bb = __ldcg(&g_sb[(size_t)(b * NC + cls) * R + (w << 5) + j]);
                        float* o = out + b * (KPAD * 5) + slot * 5;
                        o[0] = bb.x; o[1] = bb.y; o[2] = bb.z; o[3] = bb.w;
                        o[4] = clsf;
                        slot++;
                    }
                }
            }
            if (lane == 0) {
                int nbase = BATCH * KPAD * 5;
                if (out_size >= nbase + BATCH)
                    out[nbase + b] = (float)min(total, KPAD);
                g_ctr[b] = 0;   // self-reset for next graph replay
            }
        }
    }
}

extern "C" void kernel_launch(void* const* d_in, const int* in_sizes, int n_in,
                              void* d_out, int out_size)
{
    (void)in_sizes; (void)n_in;
    const float* cls_prob  = (const float*)d_in[0];
    const float* rois      = (const float*)d_in[1];
    const float* bbox_pred = (const float*)d_in[2];
    const float* im_info   = (const float*)d_in[3];
    const float* thr       = (const float*)d_in[4];

    fused_nms_kernel<<<BATCH * NC, NT>>>(cls_prob, rois, bbox_pred, im_info, thr,
                                         (float*)d_out, out_size);
}

// round 5
// speedup vs baseline: 3.5568x; 1.1691x over previous
#include <cuda_runtime.h>
#include <math.h>

// Problem constants (shapes fixed by the dataset)
#define BATCH 8
#define R 300
#define C 21
#define NC 20           // foreground classes
#define KPAD 21         // output pad size == num_classes
#define RW 10           // ceil(300/32) keep-bitmask words
#define NMS_T 0.3f
#define NT 512          // threads per block
#define NW 16           // warps per block

// Cross-block intermediates (allocation-free rule: device globals)
__device__ float4   g_sb[BATCH * NC * R];      // sorted+clipped boxes per (b,class)
__device__ unsigned g_keep[BATCH * NC * RW];   // keep bitmask per (b,class)
__device__ int      g_ctr[BATCH];              // arrival counters (self-resetting)

__global__ __launch_bounds__(NT) void fused_nms_kernel(
    const float* __restrict__ cls_prob,   // [B,R,C]
    const float* __restrict__ rois,       // [B,R,5]
    const float* __restrict__ bbox_pred,  // [B,R,4C]
    const float* __restrict__ im_info,    // [B,3]
    const float* __restrict__ thr_arr,    // [C]
    float* __restrict__ out, int out_size)
{
    __shared__ unsigned long long ckeys[R];   // compacted valid keys, index order
    __shared__ float4  box_sh[R];             // decoded boxes by original index
    __shared__ float4  sb_sh[R];              // boxes in sorted order (valid prefix)
    __shared__ float   area_sh[R];            // areas in sorted order
    __shared__ unsigned mask_sh[R][RW];       // suppression bitmask (valid prefix)
    __shared__ int warpcnt[NW];
    __shared__ int warpoff[NW];
    __shared__ int sV;
    __shared__ int sOld;
    // peeling-NMS state
    __shared__ unsigned slive[RW], skept[RW], sinc[RW], sknew[RW], ssup[RW];
    __shared__ int sAlive;
    // tail selection state
    __shared__ unsigned skw_sh[NC][RW];
    __shared__ int sexcl_sh[32];

    const int blk = blockIdx.x;
    const int b   = blk / NC;
    const int cc  = blk % NC;      // 0..19
    const int c   = cc + 1;        // class id 1..20
    const int t   = threadIdx.x;
    const int lane = t & 31;
    const int wid  = t >> 5;

    const float thr = thr_arr[c];
    const float H1 = im_info[b * 3 + 0] - 1.0f;
    const float W1 = im_info[b * 3 + 1] - 1.0f;

    // ---- decode + clip + key (one row per thread; arithmetic identical to R1) ----
    int valid = 0;
    unsigned long long key = ~0ULL;
    const int r = t;
    if (r < R) {
        const float* rp = rois + (size_t)(b * R + r) * 5;
        float x1 = rp[1], y1 = rp[2], x2 = rp[3], y2 = rp[4];
        float w  = x2 - x1 + 1.0f;
        float h  = y2 - y1 + 1.0f;
        float cx = x1 + 0.5f * w;
        float cy = y1 + 0.5f * h;

        const float* dp = bbox_pred + (size_t)(b * R + r) * (4 * C) + 4 * c;
        float d0 = dp[0] * 0.1f;
        float d1 = dp[1] * 0.1f;
        float d2 = dp[2] * 0.2f;
        float d3 = dp[3] * 0.2f;

        float pcx = d0 * w + cx;
        float pcy = d1 * h + cy;
        float pw  = expf(d2) * w;
        float ph  = expf(d3) * h;

        float bx1 = fminf(fmaxf(pcx - 0.5f * pw, 0.0f), W1);
        float by1 = fminf(fmaxf(pcy - 0.5f * ph, 0.0f), H1);
        float bx2 = fminf(fmaxf(pcx + 0.5f * pw, 0.0f), W1);
        float by2 = fminf(fmaxf(pcy + 0.5f * ph, 0.0f), H1);
        box_sh[r] = make_float4(bx1, by1, bx2, by2);

        float s = cls_prob[(size_t)(b * R + r) * C + c];
        valid = (s > thr) ? 1 : 0;

        // monotone float->uint, inverted => ascending sort == descending score,
        // low 32 bits = original index (stable tie-break).
        unsigned u = __float_as_uint(s);
        unsigned m = (u & 0x80000000u) ? ~u : (u | 0x80000000u);
        key = (((unsigned long long)(~m)) << 32) | (unsigned)r;
    }

    // ---- stable compaction of valid rows (index order preserved) ----
    unsigned bal = __ballot_sync(0xffffffffu, valid);
    if (lane == 0) warpcnt[wid] = __popc(bal);
    __syncthreads();
    if (t < NW) {
        int v = warpcnt[t];
        int incl = v;
        #pragma unroll
        for (int off = 1; off < NW; off <<= 1) {
            int n = __shfl_up_sync(0x0000ffffu, incl, off);
            if (t >= off) incl += n;
        }
        warpoff[t] = incl - v;
        if (t == NW - 1) sV = incl;
    }
    __syncthreads();
    const int V  = sV;
    const int VW = (V + 31) >> 5;

    if (valid) {
        int pos = warpoff[wid] + __popc(bal & ((1u << lane) - 1u));
        ckeys[pos] = key;
    }
    __syncthreads();

    // ---- enumeration (rank) sort over the V compacted keys ----
    if (t < V) {
        unsigned long long k0 = ckeys[t];
        int rank = 0;
        #pragma unroll 4
        for (int j = 0; j < V; j++)
            rank += (ckeys[j] < k0);
        int orig = (int)(k0 & 0xFFFFFFFFu);
        float4 bb = box_sh[orig];
        sb_sh[rank] = bb;
        area_sh[rank] = (bb.z - bb.x + 1.0f) * (bb.w - bb.y + 1.0f);
    }
    // pre-zero mask rows (peeling reads full rows, including below-diagonal words)
    for (int idx = t; idx < V * RW; idx += NT)
        ((unsigned*)mask_sh)[idx] = 0u;
    __syncthreads();

    // ---- publish sorted boxes (valid prefix) for cross-block selection ----
    if (t < V)
        __stcg(&g_sb[(size_t)(b * NC + cc) * R + t], sb_sh[t]);

    // ---- suppression bitmask on the valid prefix, warp-ballot per 32-j chunk ----
    for (int i = wid; i < V; i += NW) {
        float4 bi = sb_sh[i];
        float  ai = area_sh[i];
        for (int jw = (i >> 5); jw < VW; jw++) {
            int j = (jw << 5) + lane;
            bool sup = false;
            if (j > i && j < V) {
                float4 bj = sb_sh[j];
                float ix1 = fmaxf(bi.x, bj.x);
                float iy1 = fmaxf(bi.y, bj.y);
                float ix2 = fminf(bi.z, bj.z);
                float iy2 = fminf(bi.w, bj.w);
                float iw = fmaxf(ix2 - ix1 + 1.0f, 0.0f);
                float ih = fmaxf(iy2 - iy1 + 1.0f, 0.0f);
                float inter = iw * ih;
                float iou = inter / (ai + area_sh[j] - inter);
                sup = (iou > NMS_T);
            }
            unsigned bits = __ballot_sync(0xffffffffu, sup);
            if (lane == 0) mask_sh[i][jw] = bits;
        }
    }

    // ---- init peeling state ----
    if (t < RW) {
        int lo = t << 5, hi = min(V, lo + 32);
        unsigned lv = 0;
        if (hi > lo) lv = (hi - lo == 32) ? 0xffffffffu : ((1u << (hi - lo)) - 1u);
        slive[t] = lv;
        skept[t] = 0u;
    }
    if (t == 0) sAlive = (V > 0) ? 1 : 0;
    __syncthreads();

    // ---- exact parallel peeling NMS ----
    // Round: keep every live box with no incoming suppression edge from a live
    // earlier box (greedy provably keeps these); remove boxes suppressed by the
    // newly kept; repeat. The earliest live box always qualifies -> progress.
    while (sAlive) {
        unsigned acc = 0;
        if (wid < RW) {
            for (int i = lane; i < V; i += 32)
                if ((slive[i >> 5] >> (i & 31)) & 1u) acc |= mask_sh[i][wid];
            #pragma unroll
            for (int off = 16; off > 0; off >>= 1)
                acc |= __shfl_down_sync(0xffffffffu, acc, off);
            if (lane == 0) sinc[wid] = acc;
        }
        __syncthreads();
        if (t < RW) {
            unsigned kn = slive[t] & ~sinc[t];
            sknew[t] = kn;
            skept[t] |= kn;
        }
        __syncthreads();
        acc = 0;
        if (wid < RW) {
            for (int i = lane; i < V; i += 32)
                if ((sknew[i >> 5] >> (i & 31)) & 1u) acc |= mask_sh[i][wid];
            #pragma unroll
            for (int off = 16; off > 0; off >>= 1)
                acc |= __shfl_down_sync(0xffffffffu, acc, off);
            if (lane == 0) ssup[wid] = acc;
        }
        if (t == 0) sAlive = 0;
        __syncthreads();
        if (t < RW) {
            unsigned nl = slive[t] & sinc[t] & ~ssup[t];
            slive[t] = nl;
            if (nl) atomicOr(&sAlive, 1);
        }
        __syncthreads();
    }
    if (t < RW)
        __stcg(&g_keep[(b * NC + cc) * RW + t], skept[t]);

    // ---- release writes, arrive; last block per image does selection ----
    __threadfence();
    __syncthreads();
    if (t == 0) {
        sOld = atomicAdd(&g_ctr[b], 1);
        __threadfence();
    }
    __syncthreads();

    if (sOld == NC - 1 && t < 32) {
        int cls = lane;     // 0..19 valid
        int cnt = 0;
        if (cls < NC) {
            #pragma unroll
            for (int w = 0; w < RW; w++) {
                unsigned kwv = __ldcg(&g_keep[(b * NC + cls) * RW + w]);
                skw_sh[cls][w] = kwv;
                cnt += __popc(kwv);
            }
        }
        // warp inclusive scan of counts
        int incl = cnt;
        #pragma unroll
        for (int off = 1; off < 32; off <<= 1) {
            int n = __shfl_up_sync(0xffffffffu, incl, off);
            if (lane >= off) incl += n;
        }
        int total = __shfl_sync(0xffffffffu, incl, 31);
        sexcl_sh[lane] = incl - cnt;
        __syncwarp();

        // zero this image's [K,5] slab
        for (int i = lane; i < KPAD * 5; i += 32)
            out[b * (KPAD * 5) + i] = 0.0f;
        __syncwarp();

        // slot-parallel emit: lane s owns output slot s
        int s = lane;
        int lim = min(total, KPAD);
        if (s < lim) {
            // find class: largest cl with sexcl_sh[cl] <= s (sexcl non-decreasing)
            int cl = 0;
            #pragma unroll
            for (int c2 = 1; c2 < NC; c2++)
                if (sexcl_sh[c2] <= s) cl = c2;
            int q = s - sexcl_sh[cl];
            // find q-th set bit across this class's keep words
            int w = 0;
            #pragma unroll
            for (int ww = 0; ww < RW; ww++) {
                int pc = __popc(skw_sh[cl][ww]);
                bool here = (q < pc);
                if (!here) q -= pc; else if (w == 0 && here) {}
                if (here) { w = ww; break; }
            }
            unsigned word = skw_sh[cl][w];
            #pragma unroll
            for (int k = 0; k < 31; k++)
                if (k < q) word &= word - 1u;
            int bit = __ffs(word) - 1;
            float4 bb = __ldcg(&g_sb[(size_t)(b * NC + cl) * R + (w << 5) + bit]);
            float* o = out + b * (KPAD * 5) + s * 5;
            o[0] = bb.x; o[1] = bb.y; o[2] = bb.z; o[3] = bb.w;
            o[4] = (float)(cl + 1);
        }
        if (lane == 0) {
            int nbase = BATCH * KPAD * 5;
            if (out_size >= nbase + BATCH)
                out[nbase + b] = (float)lim;
            g_ctr[b] = 0;   // self-reset for next graph replay
        }
    }
}

extern "C" void kernel_launch(void* const* d_in, const int* in_sizes, int n_in,
                              void* d_out, int out_size)
{
    (void)in_sizes; (void)n_in;
    const float* cls_prob  = (const float*)d_in[0];
    const float* rois      = (const float*)d_in[1];
    const float* bbox_pred = (const float*)d_in[2];
    const float* im_info   = (const float*)d_in[3];
    const float* thr       = (const float*)d_in[4];

    fused_nms_kernel<<<BATCH * NC, NT>>>(cls_prob, rois, bbox_pred, im_info, thr,
                                         (float*)d_out, out_size);
}

// round 6
// speedup vs baseline: 4.5668x; 1.2840x over previous
#include <cuda_runtime.h>
#include <math.h>

// Problem constants (shapes fixed by the dataset)
#define BATCH 8
#define R 300
#define C 21
#define NC 20           // foreground classes
#define KPAD 21         // output pad size == num_classes
#define RW 10           // ceil(300/32) keep-bitmask words
#define NMS_T 0.3f
#define NT 512          // threads per block
#define NW 16           // warps per block

// Cross-block intermediates (allocation-free rule: device globals)
__device__ float4   g_sb[BATCH * NC * R];      // sorted+clipped boxes per (b,class)
__device__ unsigned g_keep[BATCH * NC * RW];   // keep bitmask per (b,class)
__device__ int      g_ctr[BATCH];              // arrival counters (self-resetting)

__global__ __launch_bounds__(NT) void fused_nms_kernel(
    const float* __restrict__ cls_prob,   // [B,R,C]
    const float* __restrict__ rois,       // [B,R,5]
    const float* __restrict__ bbox_pred,  // [B,R,4C]
    const float* __restrict__ im_info,    // [B,3]
    const float* __restrict__ thr_arr,    // [C]
    float* __restrict__ out, int out_size)
{
    __shared__ unsigned long long ckeys[R];   // compacted valid keys, index order
    __shared__ float4  box_sh[R];             // decoded boxes by original index
    __shared__ float4  sb_sh[R];              // boxes in sorted order (valid prefix)
    __shared__ float   area_sh[R];            // areas in sorted order
    __shared__ unsigned mask_sh[R][RW];       // suppression bitmask (valid prefix)
    __shared__ int warpcnt[NW];
    __shared__ int warpoff[NW];
    __shared__ int sV;
    __shared__ int sOld;
    // peeling-NMS state
    __shared__ unsigned slive[RW], skept[RW], sinc[RW], sknew[RW], ssup[RW];
    __shared__ int sAlive;
    // tail selection state
    __shared__ unsigned skw_sh[NC][RW];
    __shared__ int sexcl_sh[32];

    const int blk = blockIdx.x;
    const int b   = blk / NC;
    const int cc  = blk % NC;      // 0..19
    const int c   = cc + 1;        // class id 1..20
    const int t   = threadIdx.x;
    const int lane = t & 31;
    const int wid  = t >> 5;

    const float thr = thr_arr[c];
    const float H1 = im_info[b * 3 + 0] - 1.0f;
    const float W1 = im_info[b * 3 + 1] - 1.0f;

    // ---- decode + clip + key (one row per thread; arithmetic identical to R1) ----
    int valid = 0;
    unsigned long long key = ~0ULL;
    const int r = t;
    if (r < R) {
        const float* rp = rois + (size_t)(b * R + r) * 5;
        float x1 = rp[1], y1 = rp[2], x2 = rp[3], y2 = rp[4];
        float w  = x2 - x1 + 1.0f;
        float h  = y2 - y1 + 1.0f;
        float cx = x1 + 0.5f * w;
        float cy = y1 + 0.5f * h;

        const float* dp = bbox_pred + (size_t)(b * R + r) * (4 * C) + 4 * c;
        float d0 = dp[0] * 0.1f;
        float d1 = dp[1] * 0.1f;
        float d2 = dp[2] * 0.2f;
        float d3 = dp[3] * 0.2f;

        float pcx = d0 * w + cx;
        float pcy = d1 * h + cy;
        float pw  = expf(d2) * w;
        float ph  = expf(d3) * h;

        float bx1 = fminf(fmaxf(pcx - 0.5f * pw, 0.0f), W1);
        float by1 = fminf(fmaxf(pcy - 0.5f * ph, 0.0f), H1);
        float bx2 = fminf(fmaxf(pcx + 0.5f * pw, 0.0f), W1);
        float by2 = fminf(fmaxf(pcy + 0.5f * ph, 0.0f), H1);
        box_sh[r] = make_float4(bx1, by1, bx2, by2);

        float s = cls_prob[(size_t)(b * R + r) * C + c];
        valid = (s > thr) ? 1 : 0;

        // monotone float->uint, inverted => ascending sort == descending score,
        // low 32 bits = original index (stable tie-break).
        unsigned u = __float_as_uint(s);
        unsigned m = (u & 0x80000000u) ? ~u : (u | 0x80000000u);
        key = (((unsigned long long)(~m)) << 32) | (unsigned)r;
    }

    // ---- stable compaction of valid rows (index order preserved) ----
    unsigned bal = __ballot_sync(0xffffffffu, valid);
    if (lane == 0) warpcnt[wid] = __popc(bal);
    __syncthreads();
    if (t < NW) {
        int v = warpcnt[t];
        int incl = v;
        #pragma unroll
        for (int off = 1; off < NW; off <<= 1) {
            int n = __shfl_up_sync(0x0000ffffu, incl, off);
            if (t >= off) incl += n;
        }
        warpoff[t] = incl - v;
        if (t == NW - 1) sV = incl;
    }
    __syncthreads();
    const int V  = sV;
    const int VW = (V + 31) >> 5;

    if (valid) {
        int pos = warpoff[wid] + __popc(bal & ((1u << lane) - 1u));
        ckeys[pos] = key;
    }
    __syncthreads();

    // ---- enumeration (rank) sort over the V compacted keys ----
    if (V > 0) {
        if (V <= 256) {
            // 2 threads per key: even counts [0,Vh), odd counts [Vh,V)
            int p = t >> 1;
            int pc = (p < V) ? p : (V - 1);
            unsigned long long kp = ckeys[pc];
            int half = t & 1;
            int Vh = (V + 1) >> 1;
            int jlo = half ? Vh : 0;
            int jhi = half ? V : Vh;
            int rk = 0;
            #pragma unroll 4
            for (int j = jlo; j < jhi; j++)
                rk += (ckeys[j] < kp);
            rk += __shfl_xor_sync(0xffffffffu, rk, 1);
            if (half == 0 && p < V) {
                int orig = (int)(kp & 0xFFFFFFFFu);
                float4 bb = box_sh[orig];
                sb_sh[rk] = bb;
                area_sh[rk] = (bb.z - bb.x + 1.0f) * (bb.w - bb.y + 1.0f);
            }
        } else {
            if (t < V) {
                unsigned long long kp = ckeys[t];
                int rk = 0;
                #pragma unroll 4
                for (int j = 0; j < V; j++)
                    rk += (ckeys[j] < kp);
                int orig = (int)(kp & 0xFFFFFFFFu);
                float4 bb = box_sh[orig];
                sb_sh[rk] = bb;
                area_sh[rk] = (bb.z - bb.x + 1.0f) * (bb.w - bb.y + 1.0f);
            }
        }
    }
    // pre-zero mask rows (peeling reads full rows, including below-diagonal words)
    for (int idx = t; idx < V * RW; idx += NT)
        ((unsigned*)mask_sh)[idx] = 0u;
    __syncthreads();

    // ---- publish sorted boxes (valid prefix) for cross-block selection ----
    if (t < V)
        __stcg(&g_sb[(size_t)(b * NC + cc) * R + t], sb_sh[t]);

    // ---- suppression bitmask on the valid prefix, warp-ballot per 32-j chunk ----
    // Division-free IoU compare with exact-fallback guard:
    //   iou > T  <=>  inter - T*union > 0 (reals). When the margin is larger
    //   than combined rounding (1e-5 * union >> 1ulp), the fast form is exact;
    //   otherwise evaluate the reference's literal (inter/union) > T.
    for (int i = wid; i < V; i += NW) {
        float4 bi = sb_sh[i];
        float  ai = area_sh[i];
        for (int jw = (i >> 5); jw < VW; jw++) {
            int j = (jw << 5) + lane;
            bool sup = false;
            if (j > i && j < V) {
                float4 bj = sb_sh[j];
                float ix1 = fmaxf(bi.x, bj.x);
                float iy1 = fmaxf(bi.y, bj.y);
                float ix2 = fminf(bi.z, bj.z);
                float iy2 = fminf(bi.w, bj.w);
                float iw = fmaxf(ix2 - ix1 + 1.0f, 0.0f);
                float ih = fmaxf(iy2 - iy1 + 1.0f, 0.0f);
                float inter = iw * ih;
                float un   = ai + area_sh[j] - inter;
                float diff = inter - NMS_T * un;
                sup = diff > 0.0f;
                if (fabsf(diff) <= 1e-5f * un)
                    sup = (inter / un) > NMS_T;   // rare exact fallback
            }
            unsigned bits = __ballot_sync(0xffffffffu, sup);
            if (lane == 0) mask_sh[i][jw] = bits;
        }
    }

    // ---- init peeling state ----
    if (t < RW) {
        int lo = t << 5, hi = min(V, lo + 32);
        unsigned lv = 0;
        if (hi > lo) lv = (hi - lo == 32) ? 0xffffffffu : ((1u << (hi - lo)) - 1u);
        slive[t] = lv;
        skept[t] = 0u;
    }
    if (t == 0) sAlive = (V > 0) ? 1 : 0;
    __syncthreads();

    // ---- exact parallel peeling NMS ----
    while (sAlive) {
        unsigned acc = 0;
        if (wid < RW) {
            for (int i = lane; i < V; i += 32)
                if ((slive[i >> 5] >> (i & 31)) & 1u) acc |= mask_sh[i][wid];
            #pragma unroll
            for (int off = 16; off > 0; off >>= 1)
                acc |= __shfl_down_sync(0xffffffffu, acc, off);
            if (lane == 0) sinc[wid] = acc;
        }
        __syncthreads();
        if (t < RW) {
            unsigned kn = slive[t] & ~sinc[t];
            sknew[t] = kn;
            skept[t] |= kn;
        }
        __syncthreads();
        acc = 0;
        if (wid < RW) {
            for (int i = lane; i < V; i += 32)
                if ((sknew[i >> 5] >> (i & 31)) & 1u) acc |= mask_sh[i][wid];
            #pragma unroll
            for (int off = 16; off > 0; off >>= 1)
                acc |= __shfl_down_sync(0xffffffffu, acc, off);
            if (lane == 0) ssup[wid] = acc;
        }
        if (t == 0) sAlive = 0;
        __syncthreads();
        if (t < RW) {
            unsigned nl = slive[t] & sinc[t] & ~ssup[t];
            slive[t] = nl;
            if (nl) atomicOr(&sAlive, 1);
        }
        __syncthreads();
    }
    if (t < RW)
        __stcg(&g_keep[(b * NC + cc) * RW + t], skept[t]);

    // ---- release writes, arrive; last block per image does selection ----
    __threadfence();
    __syncthreads();
    if (t == 0) {
        sOld = atomicAdd(&g_ctr[b], 1);
        __threadfence();
    }
    __syncthreads();

    if (sOld == NC - 1 && t < 32) {
        int cls = lane;     // 0..19 valid
        int cnt = 0;
        if (cls < NC) {
            #pragma unroll
            for (int w = 0; w < RW; w++) {
                unsigned kwv = __ldcg(&g_keep[(b * NC + cls) * RW + w]);
                skw_sh[cls][w] = kwv;
                cnt += __popc(kwv);
            }
        }
        // warp inclusive scan of counts
        int incl = cnt;
        #pragma unroll
        for (int off = 1; off < 32; off <<= 1) {
            int n = __shfl_up_sync(0xffffffffu, incl, off);
            if (lane >= off) incl += n;
        }
        int total = __shfl_sync(0xffffffffu, incl, 31);
        sexcl_sh[lane] = incl - cnt;
        __syncwarp();

        // zero this image's [K,5] slab
        for (int i = lane; i < KPAD * 5; i += 32)
            out[b * (KPAD * 5) + i] = 0.0f;
        __syncwarp();

        // slot-parallel emit: lane s owns output slot s
        int s = lane;
        int lim = min(total, KPAD);
        if (s < lim) {
            // find class: largest cl with sexcl_sh[cl] <= s (sexcl non-decreasing)
            int cl = 0;
            #pragma unroll
            for (int c2 = 1; c2 < NC; c2++)
                if (sexcl_sh[c2] <= s) cl = c2;
            int q = s - sexcl_sh[cl];
            // find q-th set bit across this class's keep words
            int w = 0;
            #pragma unroll
            for (int ww = 0; ww < RW; ww++) {
                int pc = __popc(skw_sh[cl][ww]);
                bool here = (q < pc);
                if (!here) q -= pc;
                if (here) { w = ww; break; }
            }
            unsigned word = skw_sh[cl][w];
            #pragma unroll
            for (int k = 0; k < 31; k++)
                if (k < q) word &= word - 1u;
            int bit = __ffs(word) - 1;
            float4 bb = __ldcg(&g_sb[(size_t)(b * NC + cl) * R + (w << 5) + bit]);
            float* o = out + b * (KPAD * 5) + s * 5;
            o[0] = bb.x; o[1] = bb.y; o[2] = bb.z; o[3] = bb.w;
            o[4] = (float)(cl + 1);
        }
        if (lane == 0) {
            int nbase = BATCH * KPAD * 5;
            if (out_size >= nbase + BATCH)
                out[nbase + b] = (float)lim;
            g_ctr[b] = 0;   // self-reset for next graph replay
        }
    }
}

extern "C" void kernel_launch(void* const* d_in, const int* in_sizes, int n_in,
                              void* d_out, int out_size)
{
    (void)in_sizes; (void)n_in;
    const float* cls_prob  = (const float*)d_in[0];
    const float* rois      = (const float*)d_in[1];
    const float* bbox_pred = (const float*)d_in[2];
    const float* im_info   = (const float*)d_in[3];
    const float* thr       = (const float*)d_in[4];

    fused_nms_kernel<<<BATCH * NC, NT>>>(cls_prob, rois, bbox_pred, im_info, thr,
                                         (float*)d_out, out_size);
}

// round 7
// speedup vs baseline: 4.9232x; 1.0780x over previous
#include <cuda_runtime.h>
#include <math.h>

// Problem constants (shapes fixed by the dataset)
#define BATCH 8
#define R 300
#define C 21
#define NC 20           // foreground classes
#define KPAD 21         // output pad size == num_classes
#define RW 10           // ceil(300/32) keep-bitmask words
#define NMS_T 0.3f
#define NT 512          // threads per block
#define NW 16           // warps per block

// Cross-block intermediates (allocation-free rule: device globals)
__device__ float4   g_sb[BATCH * NC * R];      // sorted+clipped boxes per (b,class)
__device__ unsigned g_keep[BATCH * NC * RW];   // keep bitmask per (b,class)
__device__ int      g_ctr[BATCH];              // arrival counters (self-resetting)

__global__ __launch_bounds__(NT, 2) void fused_nms_kernel(
    const float* __restrict__ cls_prob,   // [B,R,C]
    const float* __restrict__ rois,       // [B,R,5]
    const float* __restrict__ bbox_pred,  // [B,R,4C]
    const float* __restrict__ im_info,    // [B,3]
    const float* __restrict__ thr_arr,    // [C]
    float* __restrict__ out, int out_size)
{
    __shared__ unsigned long long ckeys[R];   // compacted valid keys, index order
    __shared__ float4  box_sh[R];             // decoded boxes by original index
    __shared__ float4  sb_sh[R];              // boxes in sorted order (valid prefix)
    __shared__ float   area_sh[R];            // areas in sorted order
    __shared__ unsigned mask_sh[R][RW];       // suppression bitmask (valid prefix)
    __shared__ int warpcnt[NW];
    __shared__ int warpoff[NW];
    __shared__ int sV;
    __shared__ int sOld;
    // peeling-NMS state
    __shared__ unsigned slive[RW], skept[RW], sinc[RW], sknew[RW], ssup[RW];
    __shared__ int sAlive;
    // tail selection state
    __shared__ unsigned skw_sh[NC][RW];
    __shared__ int sexcl_sh[32];

    const int blk = blockIdx.x;
    const int b   = blk / NC;
    const int cc  = blk % NC;      // 0..19
    const int c   = cc + 1;        // class id 1..20
    const int t   = threadIdx.x;
    const int lane = t & 31;
    const int wid  = t >> 5;

    const float thr = thr_arr[c];
    const float H1 = im_info[b * 3 + 0] - 1.0f;
    const float W1 = im_info[b * 3 + 1] - 1.0f;

    // ---- decode + clip + key (one row per thread; arithmetic identical to R1) ----
    int valid = 0;
    unsigned long long key = ~0ULL;
    const int r = t;
    if (r < R) {
        const float* rp = rois + (size_t)(b * R + r) * 5;
        float x1 = rp[1], y1 = rp[2], x2 = rp[3], y2 = rp[4];
        float w  = x2 - x1 + 1.0f;
        float h  = y2 - y1 + 1.0f;
        float cx = x1 + 0.5f * w;
        float cy = y1 + 0.5f * h;

        // 16B-aligned: byte offset = 336*(b*R+r) + 16*c
        const float4 d4 = *reinterpret_cast<const float4*>(
            bbox_pred + (size_t)(b * R + r) * (4 * C) + 4 * c);
        float d0 = d4.x * 0.1f;
        float d1 = d4.y * 0.1f;
        float d2 = d4.z * 0.2f;
        float d3 = d4.w * 0.2f;

        float pcx = d0 * w + cx;
        float pcy = d1 * h + cy;
        float pw  = expf(d2) * w;
        float ph  = expf(d3) * h;

        float bx1 = fminf(fmaxf(pcx - 0.5f * pw, 0.0f), W1);
        float by1 = fminf(fmaxf(pcy - 0.5f * ph, 0.0f), H1);
        float bx2 = fminf(fmaxf(pcx + 0.5f * pw, 0.0f), W1);
        float by2 = fminf(fmaxf(pcy + 0.5f * ph, 0.0f), H1);
        box_sh[r] = make_float4(bx1, by1, bx2, by2);

        float s = cls_prob[(size_t)(b * R + r) * C + c];
        valid = (s > thr) ? 1 : 0;

        // monotone float->uint, inverted => ascending sort == descending score,
        // low 32 bits = original index (stable tie-break).
        unsigned u = __float_as_uint(s);
        unsigned m = (u & 0x80000000u) ? ~u : (u | 0x80000000u);
        key = (((unsigned long long)(~m)) << 32) | (unsigned)r;
    }

    // ---- stable compaction of valid rows (index order preserved) ----
    unsigned bal = __ballot_sync(0xffffffffu, valid);
    if (lane == 0) warpcnt[wid] = __popc(bal);
    __syncthreads();
    if (t < NW) {
        int v = warpcnt[t];
        int incl = v;
        #pragma unroll
        for (int off = 1; off < NW; off <<= 1) {
            int n = __shfl_up_sync(0x0000ffffu, incl, off);
            if (t >= off) incl += n;
        }
        warpoff[t] = incl - v;
        if (t == NW - 1) sV = incl;
    }
    __syncthreads();
    const int V  = sV;
    const int VW = (V + 31) >> 5;

    if (valid) {
        int pos = warpoff[wid] + __popc(bal & ((1u << lane) - 1u));
        ckeys[pos] = key;
    }
    __syncthreads();

    // ---- enumeration (rank) sort over the V compacted keys ----
    if (V > 0) {
        if (V <= 256) {
            // 2 threads per key: even counts [0,Vh), odd counts [Vh,V)
            int p = t >> 1;
            int pc = (p < V) ? p : (V - 1);
            unsigned long long kp = ckeys[pc];
            int half = t & 1;
            int Vh = (V + 1) >> 1;
            int jlo = half ? Vh : 0;
            int jhi = half ? V : Vh;
            int rk = 0;
            #pragma unroll 4
            for (int j = jlo; j < jhi; j++)
                rk += (ckeys[j] < kp);
            rk += __shfl_xor_sync(0xffffffffu, rk, 1);
            if (half == 0 && p < V) {
                int orig = (int)(kp & 0xFFFFFFFFu);
                float4 bb = box_sh[orig];
                sb_sh[rk] = bb;
                area_sh[rk] = (bb.z - bb.x + 1.0f) * (bb.w - bb.y + 1.0f);
            }
        } else {
            if (t < V) {
                unsigned long long kp = ckeys[t];
                int rk = 0;
                #pragma unroll 4
                for (int j = 0; j < V; j++)
                    rk += (ckeys[j] < kp);
                int orig = (int)(kp & 0xFFFFFFFFu);
                float4 bb = box_sh[orig];
                sb_sh[rk] = bb;
                area_sh[rk] = (bb.z - bb.x + 1.0f) * (bb.w - bb.y + 1.0f);
            }
        }
    }
    // pre-zero mask rows (peeling reads full rows, including below-diagonal words)
    for (int idx = t; idx < V * RW; idx += NT)
        ((unsigned*)mask_sh)[idx] = 0u;
    __syncthreads();

    // ---- publish sorted boxes (valid prefix) for cross-block selection ----
    if (t < V)
        __stcg(&g_sb[(size_t)(b * NC + cc) * R + t], sb_sh[t]);

    // ---- suppression bitmask, paired rows per warp, division-free compare ----
    //   iou > T  <=>  (1+T)*inter - T*(ai+aj) > 0 (reals). When |diff| is larger
    //   than 1e-5 * union (>> combined rounding), the fast form is exact;
    //   otherwise evaluate the reference's literal (inter/union) > T.
    for (int i = wid; i < V; i += 2 * NW) {
        const int i2 = i + NW;
        const bool has2 = (i2 < V);
        float4 bi  = sb_sh[i];
        float  ai  = area_sh[i];
        float4 bi2 = sb_sh[has2 ? i2 : i];
        float  ai2 = area_sh[has2 ? i2 : i];
        for (int jw = (i >> 5); jw < VW; jw++) {
            int j  = (jw << 5) + lane;
            int jc = (j < V) ? j : (V - 1);
            float4 bj = sb_sh[jc];
            float  aj = area_sh[jc];

            bool sup1 = false, sup2 = false;
            {
                float ix1 = fmaxf(bi.x, bj.x);
                float iy1 = fmaxf(bi.y, bj.y);
                float ix2 = fminf(bi.z, bj.z);
                float iy2 = fminf(bi.w, bj.w);
                float iw = fmaxf(ix2 - ix1 + 1.0f, 0.0f);
                float ih = fmaxf(iy2 - iy1 + 1.0f, 0.0f);
                float inter = iw * ih;
                float asum = ai + aj;
                float diff = fmaf(inter, 1.0f + NMS_T, -NMS_T * asum);
                bool s1 = diff > 0.0f;
                float un = asum - inter;
                if (fabsf(diff) <= 1e-5f * un)
                    s1 = (inter / un) > NMS_T;   // rare exact fallback
                sup1 = s1 && (j > i) && (j < V);
            }
            {
                float ix1 = fmaxf(bi2.x, bj.x);
                float iy1 = fmaxf(bi2.y, bj.y);
                float ix2 = fminf(bi2.z, bj.z);
                float iy2 = fminf(bi2.w, bj.w);
                float iw = fmaxf(ix2 - ix1 + 1.0f, 0.0f);
                float ih = fmaxf(iy2 - iy1 + 1.0f, 0.0f);
                float inter = iw * ih;
                float asum = ai2 + aj;
                float diff = fmaf(inter, 1.0f + NMS_T, -NMS_T * asum);
                bool s2 = diff > 0.0f;
                float un = asum - inter;
                if (fabsf(diff) <= 1e-5f * un)
                    s2 = (inter / un) > NMS_T;   // rare exact fallback
                sup2 = s2 && has2 && (j > i2) && (j < V);
            }
            unsigned bits1 = __ballot_sync(0xffffffffu, sup1);
            unsigned bits2 = __ballot_sync(0xffffffffu, sup2);
            if (lane == 0) {
                mask_sh[i][jw] = bits1;
                if (has2) mask_sh[i2][jw] = bits2;   // zero below diagonal: harmless
            }
        }
    }

    // ---- init peeling state ----
    if (t < RW) {
        int lo = t << 5, hi = min(V, lo + 32);
        unsigned lv = 0;
        if (hi > lo) lv = (hi - lo == 32) ? 0xffffffffu : ((1u << (hi - lo)) - 1u);
        slive[t] = lv;
        skept[t] = 0u;
    }
    if (t == 0) sAlive = (V > 0) ? 1 : 0;
    __syncthreads();

    // ---- exact parallel peeling NMS ----
    while (sAlive) {
        unsigned acc = 0;
        if (wid < RW) {
            for (int i = lane; i < V; i += 32)
                if ((slive[i >> 5] >> (i & 31)) & 1u) acc |= mask_sh[i][wid];
            #pragma unroll
            for (int off = 16; off > 0; off >>= 1)
                acc |= __shfl_down_sync(0xffffffffu, acc, off);
            if (lane == 0) sinc[wid] = acc;
        }
        __syncthreads();
        if (t < RW) {
            unsigned kn = slive[t] & ~sinc[t];
            sknew[t] = kn;
            skept[t] |= kn;
        }
        __syncthreads();
        acc = 0;
        if (wid < RW) {
            for (int i = lane; i < V; i += 32)
                if ((sknew[i >> 5] >> (i & 31)) & 1u) acc |= mask_sh[i][wid];
            #pragma unroll
            for (int off = 16; off > 0; off >>= 1)
                acc |= __shfl_down_sync(0xffffffffu, acc, off);
            if (lane == 0) ssup[wid] = acc;
        }
        if (t == 0) sAlive = 0;
        __syncthreads();
        if (t < RW) {
            unsigned nl = slive[t] & sinc[t] & ~ssup[t];
            slive[t] = nl;
            if (nl) atomicOr(&sAlive, 1);
        }
        __syncthreads();
    }
    if (t < RW)
        __stcg(&g_keep[(b * NC + cc) * RW + t], skept[t]);

    // ---- release writes, arrive; last block per image does selection ----
    __threadfence();
    __syncthreads();
    if (t == 0) {
        sOld = atomicAdd(&g_ctr[b], 1);
        __threadfence();
    }
    __syncthreads();

    if (sOld == NC - 1 && t < 32) {
        int cls = lane;     // 0..19 valid
        int cnt = 0;
        if (cls < NC) {
            #pragma unroll
            for (int w = 0; w < RW; w++) {
                unsigned kwv = __ldcg(&g_keep[(b * NC + cls) * RW + w]);
                skw_sh[cls][w] = kwv;
                cnt += __popc(kwv);
            }
        }
        // warp inclusive scan of counts
        int incl = cnt;
        #pragma unroll
        for (int off = 1; off < 32; off <<= 1) {
            int n = __shfl_up_sync(0xffffffffu, incl, off);
            if (lane >= off) incl += n;
        }
        int total = __shfl_sync(0xffffffffu, incl, 31);
        sexcl_sh[lane] = incl - cnt;
        __syncwarp();

        // zero this image's [K,5] slab
        for (int i = lane; i < KPAD * 5; i += 32)
            out[b * (KPAD * 5) + i] = 0.0f;
        __syncwarp();

        // slot-parallel emit: lane s owns output slot s
        int s = lane;
        int lim = min(total, KPAD);
        if (s < lim) {
            // find class: largest cl with sexcl_sh[cl] <= s (sexcl non-decreasing)
            int cl = 0;
            #pragma unroll
            for (int c2 = 1; c2 < NC; c2++)
                if (sexcl_sh[c2] <= s) cl = c2;
            int q = s - sexcl_sh[cl];
            // find q-th set bit across this class's keep words
            int w = 0;
            #pragma unroll
            for (int ww = 0; ww < RW; ww++) {
                int pc = __popc(skw_sh[cl][ww]);
                bool here = (q < pc);
                if (!here) q -= pc;
                if (here) { w = ww; break; }
            }
            unsigned word = skw_sh[cl][w];
            #pragma unroll
            for (int k = 0; k < 31; k++)
                if (k < q) word &= word - 1u;
            int bit = __ffs(word) - 1;
            float4 bb = __ldcg(&g_sb[(size_t)(b * NC + cl) * R + (w << 5) + bit]);
            float* o = out + b * (KPAD * 5) + s * 5;
            o[0] = bb.x; o[1] = bb.y; o[2] = bb.z; o[3] = bb.w;
            o[4] = (float)(cl + 1);
        }
        if (lane == 0) {
            int nbase = BATCH * KPAD * 5;
            if (out_size >= nbase + BATCH)
                out[nbase + b] = (float)lim;
            g_ctr[b] = 0;   // self-reset for next graph replay
        }
    }
}

extern "C" void kernel_launch(void* const* d_in, const int* in_sizes, int n_in,
                              void* d_out, int out_size)
{
    (void)in_sizes; (void)n_in;
    const float* cls_prob  = (const float*)d_in[0];
    const float* rois      = (const float*)d_in[1];
    const float* bbox_pred = (const float*)d_in[2];
    const float* im_info   = (const float*)d_in[3];
    const float* thr       = (const float*)d_in[4];

    fused_nms_kernel<<<BATCH * NC, NT>>>(cls_prob, rois, bbox_pred, im_info, thr,
                                         (float*)d_out, out_size);
}